// round 14
// baseline (speedup 1.0000x reference)
#include <cuda_runtime.h>
#include <cstdint>

#define N_TOT 8192
#define D_DIM 512

// ---------------- scratch (static device globals: allocation-free) ----------
__device__ float g_Q[N_TOT * D_DIM];
__device__ float g_K[N_TOT * D_DIM];
__device__ float g_V[N_TOT * D_DIM];
__device__ float g_S[67108864];   // 8192 * 8192
__device__ float g_roff[N_TOT];

// ---------------- helpers ---------------------------------------------------
__device__ __forceinline__ float to_tf32(float x) {
    float r;
    asm("cvt.rna.tf32.f32 %0, %1;" : "=f"(r) : "f"(x));
    return r;
}

__device__ __forceinline__ float fast_exp2(float x) {
    float y;
    asm("ex2.approx.ftz.f32 %0, %1;" : "=f"(y) : "f"(x));
    return y;
}

__device__ __forceinline__ void mma_tf32(float* c, const uint32_t* a, const uint32_t* b) {
    asm volatile(
        "mma.sync.aligned.m16n8k8.row.col.f32.tf32.tf32.f32 "
        "{%0,%1,%2,%3}, {%4,%5,%6,%7}, {%8,%9}, {%0,%1,%2,%3};\n"
        : "+f"(c[0]), "+f"(c[1]), "+f"(c[2]), "+f"(c[3])
        : "r"(a[0]), "r"(a[1]), "r"(a[2]), "r"(a[3]), "r"(b[0]), "r"(b[1]));
}

// ---------------- GEMM: split-TF32, double-buffered pipeline ----------------
// MODE 0 (NN): C[M,N] = A[M,K] @ B[K,N]        (both row-major)
// MODE 1 (NT): C[M,N] = A[M,K] @ B[N,K]^T
// LEAKY: epilogue y = x>0 ? x : 0.01x
// SOFT : prologue on A: a' = exp2(a*log2e + rowoff[row])
// NMMA : 3 -> al*bh + ah*bl + ah*bh (effective fp32)
//        2 -> al*bh + ah*bh         (A exact-split, B rounded to tf32)
// CTA tile 128x128x16, 256 threads (8 warps of 64x32 warp tiles), 2 CTAs/SM.
// 2-stage pipeline: LDG(t+1) -> compute(t) -> split+STS(t+1) -> 1 barrier.
#define BM 128
#define BN 128
#define BK 16
#define AS_STRIDE 20     // 16 + 4 pad (80B rows, 16B aligned, LDS conflict-free)
#define BS_STRIDE_NT 20
#define BS_STRIDE_NN 136 // 128 + 8 pad
#define TILE_F 2560      // floats per buffer: 128*20 (>= 16*136)

template <int MODE, bool LEAKY, bool SOFT, int NMMA>
__global__ void __launch_bounds__(256, 2)
gemm_kernel(const float* __restrict__ A, const float* __restrict__ B,
            float* __restrict__ C, int M, int N, int K,
            const float* __restrict__ rowoff) {
    extern __shared__ float smem[];
    const int NBUF = (NMMA == 3) ? 4 : 3;

    const int tid  = threadIdx.x;
    const int lane = tid & 31;
    const int warp = tid >> 5;
    const int wm   = warp >> 2;     // 0..1  (64-row slabs)
    const int wn   = warp & 3;      // 0..3  (32-col slabs)
    const int tg   = lane >> 2;     // groupID 0..7
    const int tig  = lane & 3;      // thread-in-group 0..3

    const int m0 = blockIdx.y * BM;
    const int n0 = blockIdx.x * BN;

    const float* Ablk = A + (size_t)m0 * K;
    const float* Bblk;
    if (MODE == 1) Bblk = B + (size_t)n0 * K;     // NT: rows of B are N
    else           Bblk = B + n0;                  // NN

    // staging geometry: A (and NT B): 128 rows x 16 cols -> 2 float4/thread
    const int ar  = tid >> 2;          // row 0..63 (+64 for i=1)
    const int ac4 = (tid & 3) * 4;     // float col offset within k-slice
    // NN B: 16 rows x 128 cols -> 2 float4/thread
    const int bnr = tid >> 5;          // k-row 0..7 (+8 for i=1)
    const int bnc = (tid & 31) * 4;    // col offset

    float soff[2];
    if (SOFT) {
#pragma unroll
        for (int i = 0; i < 2; i++) soff[i] = rowoff[m0 + ar + i * 64];
    }

    float acc[4][4][4];
#pragma unroll
    for (int a = 0; a < 4; a++)
#pragma unroll
        for (int b = 0; b < 4; b++)
#pragma unroll
            for (int c = 0; c < 4; c++) acc[a][b][c] = 0.f;

    const float L2E = 1.44269504088896f;
    const int T = K / BK;

    float4 a_reg[2], b_reg[2];

    // ---- LDG of tile t into registers ----
    auto ldg_tile = [&](int k0) {
#pragma unroll
        for (int i = 0; i < 2; i++)
            a_reg[i] = *(const float4*)(Ablk + (size_t)(ar + i * 64) * K + k0 + ac4);
        if (MODE == 1) {
#pragma unroll
            for (int i = 0; i < 2; i++)
                b_reg[i] = *(const float4*)(Bblk + (size_t)(ar + i * 64) * K + k0 + ac4);
        } else {
#pragma unroll
            for (int i = 0; i < 2; i++)
                b_reg[i] = *(const float4*)(Bblk + (size_t)(k0 + bnr + i * 8) * N + bnc);
        }
    };

    // ---- split + STS of registers into stage s ----
    auto sts_tile = [&](int s) {
        float* Ah = smem + (s * NBUF + 0) * TILE_F;
        float* Al = smem + (s * NBUF + 1) * TILE_F;
        float* Bh = smem + (s * NBUF + 2) * TILE_F;
        float* Bl = smem + (s * NBUF + 3) * TILE_F;   // valid only if NMMA==3
#pragma unroll
        for (int i = 0; i < 2; i++) {
            float4 v = a_reg[i];
            if (SOFT) {
                v.x = fast_exp2(fmaf(v.x, L2E, soff[i]));
                v.y = fast_exp2(fmaf(v.y, L2E, soff[i]));
                v.z = fast_exp2(fmaf(v.z, L2E, soff[i]));
                v.w = fast_exp2(fmaf(v.w, L2E, soff[i]));
            }
            float4 h, l;
            h.x = to_tf32(v.x); l.x = to_tf32(v.x - h.x);
            h.y = to_tf32(v.y); l.y = to_tf32(v.y - h.y);
            h.z = to_tf32(v.z); l.z = to_tf32(v.z - h.z);
            h.w = to_tf32(v.w); l.w = to_tf32(v.w - h.w);
            int off = (ar + i * 64) * AS_STRIDE + ac4;
            *(float4*)(&Ah[off]) = h;
            *(float4*)(&Al[off]) = l;
        }
#pragma unroll
        for (int i = 0; i < 2; i++) {
            float4 v = b_reg[i];
            float4 h;
            h.x = to_tf32(v.x); h.y = to_tf32(v.y);
            h.z = to_tf32(v.z); h.w = to_tf32(v.w);
            int off;
            if (MODE == 1) off = (ar + i * 64) * BS_STRIDE_NT + ac4;
            else           off = (bnr + i * 8) * BS_STRIDE_NN + bnc;
            *(float4*)(&Bh[off]) = h;
            if (NMMA == 3) {
                float4 l;
                l.x = to_tf32(v.x - h.x); l.y = to_tf32(v.y - h.y);
                l.z = to_tf32(v.z - h.z); l.w = to_tf32(v.w - h.w);
                *(float4*)(&Bl[off]) = l;
            }
        }
    };

    // ---- prologue: stage tile 0 ----
    ldg_tile(0);
    sts_tile(0);
    __syncthreads();

    for (int t = 0; t < T; t++) {
        const int cur = t & 1;
        const bool more = (t + 1 < T);

        if (more) ldg_tile((t + 1) * BK);   // latency hidden under compute

        // ---- compute from stage cur: 2 k-steps of 8 ----
        const float* Ah = smem + (cur * NBUF + 0) * TILE_F;
        const float* Al = smem + (cur * NBUF + 1) * TILE_F;
        const float* Bh = smem + (cur * NBUF + 2) * TILE_F;
        const float* Bl = smem + (cur * NBUF + 3) * TILE_F;
#pragma unroll
        for (int kk = 0; kk < 2; kk++) {
            const int k8 = kk * 8;
            uint32_t bh[4][2], bl[4][2];
#pragma unroll
            for (int nt = 0; nt < 4; nt++) {
                int col = wn * 32 + nt * 8 + tg;
                if (MODE == 1) {
                    int off = col * BS_STRIDE_NT + k8 + tig;
                    bh[nt][0] = __float_as_uint(Bh[off]);
                    bh[nt][1] = __float_as_uint(Bh[off + 4]);
                    if (NMMA == 3) {
                        bl[nt][0] = __float_as_uint(Bl[off]);
                        bl[nt][1] = __float_as_uint(Bl[off + 4]);
                    }
                } else {
                    int off0 = (k8 + tig)     * BS_STRIDE_NN + col;
                    int off1 = (k8 + 4 + tig) * BS_STRIDE_NN + col;
                    bh[nt][0] = __float_as_uint(Bh[off0]);
                    bh[nt][1] = __float_as_uint(Bh[off1]);
                    if (NMMA == 3) {
                        bl[nt][0] = __float_as_uint(Bl[off0]);
                        bl[nt][1] = __float_as_uint(Bl[off1]);
                    }
                }
            }
#pragma unroll
            for (int mt = 0; mt < 4; mt++) {
                int off = (wm * 64 + mt * 16 + tg) * AS_STRIDE + k8 + tig;
                uint32_t ah[4], al[4];
                ah[0] = __float_as_uint(Ah[off]);
                ah[1] = __float_as_uint(Ah[off + 8 * AS_STRIDE]);
                ah[2] = __float_as_uint(Ah[off + 4]);
                ah[3] = __float_as_uint(Ah[off + 8 * AS_STRIDE + 4]);
                al[0] = __float_as_uint(Al[off]);
                al[1] = __float_as_uint(Al[off + 8 * AS_STRIDE]);
                al[2] = __float_as_uint(Al[off + 4]);
                al[3] = __float_as_uint(Al[off + 8 * AS_STRIDE + 4]);
#pragma unroll
                for (int nt = 0; nt < 4; nt++) {
                    mma_tf32(acc[mt][nt], al, bh[nt]);                 // lo*hi
                    if (NMMA == 3) mma_tf32(acc[mt][nt], ah, bl[nt]);  // hi*lo
                    mma_tf32(acc[mt][nt], ah, bh[nt]);                 // hi*hi
                }
            }
        }

        if (more) sts_tile(cur ^ 1);        // write next stage (free buffer)
        __syncthreads();                    // one barrier per tile
    }

    // ---- epilogue ----
    float* Cblk = C + (size_t)(m0 + wm * 64) * N + n0 + wn * 32;
#pragma unroll
    for (int mt = 0; mt < 4; mt++) {
#pragma unroll
        for (int nt = 0; nt < 4; nt++) {
            int r = mt * 16 + tg;
            int c = nt * 8 + 2 * tig;
            float v0 = acc[mt][nt][0], v1 = acc[mt][nt][1];
            float v2 = acc[mt][nt][2], v3 = acc[mt][nt][3];
            if (LEAKY) {
                v0 = v0 > 0.f ? v0 : 0.01f * v0;
                v1 = v1 > 0.f ? v1 : 0.01f * v1;
                v2 = v2 > 0.f ? v2 : 0.01f * v2;
                v3 = v3 > 0.f ? v3 : 0.01f * v3;
            }
            *(float2*)(Cblk + (size_t)r * N + c)       = make_float2(v0, v1);
            *(float2*)(Cblk + (size_t)(r + 8) * N + c) = make_float2(v2, v3);
        }
    }
}

// ---------------- row stats: rowoff = -(max*log2e + log2(sum exp)) ----------
__global__ void rowstats_kernel(const float* __restrict__ S, float* __restrict__ roff) {
    __shared__ float red[8];
    const int row = blockIdx.x;
    const int tid = threadIdx.x;
    const float* p = S + (size_t)row * N_TOT;
    const float L2E = 1.44269504088896f;

    float v[32];
    float m = -3.402823e38f;
#pragma unroll
    for (int i = 0; i < 32; i++) {
        v[i] = p[tid + (i << 8)];
        m = fmaxf(m, v[i]);
    }
#pragma unroll
    for (int o = 16; o; o >>= 1) m = fmaxf(m, __shfl_xor_sync(0xffffffffu, m, o));
    if ((tid & 31) == 0) red[tid >> 5] = m;
    __syncthreads();
    m = red[0];
#pragma unroll
    for (int w = 1; w < 8; w++) m = fmaxf(m, red[w]);
    __syncthreads();

    float s = 0.f;
#pragma unroll
    for (int i = 0; i < 32; i++) s += fast_exp2((v[i] - m) * L2E);
#pragma unroll
    for (int o = 16; o; o >>= 1) s += __shfl_xor_sync(0xffffffffu, s, o);
    if ((tid & 31) == 0) red[tid >> 5] = s;
    __syncthreads();
    if (tid == 0) {
        float tot = 0.f;
#pragma unroll
        for (int w = 0; w < 8; w++) tot += red[w];
        roff[row] = -(m * L2E + __log2f(tot));
    }
}

// ---------------- launch -----------------------------------------------------
extern "C" void kernel_launch(void* const* d_in, const int* in_sizes, int n_in,
                              void* d_out, int out_size) {
    const float* x1 = (const float*)d_in[0];
    const float* x2 = (const float*)d_in[1];
    const float* wq = (const float*)d_in[2];
    const float* wk = (const float*)d_in[3];
    const float* wv = (const float*)d_in[4];
    float* out = (float*)d_out;

    float *Q, *Kp, *V, *S, *roff;
    cudaGetSymbolAddress((void**)&Q,    g_Q);
    cudaGetSymbolAddress((void**)&Kp,   g_K);
    cudaGetSymbolAddress((void**)&V,    g_V);
    cudaGetSymbolAddress((void**)&S,    g_S);
    cudaGetSymbolAddress((void**)&roff, g_roff);

    constexpr int SMEM3 = 2 * 4 * TILE_F * 4;   // 81920 B  (2 stages x {Ah,Al,Bh,Bl})
    constexpr int SMEM2 = 2 * 3 * TILE_F * 4;   // 61440 B  (2 stages x {Ah,Al,Bh})

    cudaFuncSetAttribute(gemm_kernel<0, false, false, 3>,
                         cudaFuncAttributeMaxDynamicSharedMemorySize, SMEM3);
    cudaFuncSetAttribute(gemm_kernel<1, true, false, 3>,
                         cudaFuncAttributeMaxDynamicSharedMemorySize, SMEM3);
    cudaFuncSetAttribute(gemm_kernel<0, false, true, 2>,
                         cudaFuncAttributeMaxDynamicSharedMemorySize, SMEM2);

    dim3 blk(256);
    dim3 gproj(D_DIM / BN, N_TOT / BM);   // (4, 64)
    dim3 glog(N_TOT / BN, N_TOT / BM);    // (64, 64)

    // 1. projections (3xTF32 => effectively fp32)
    gemm_kernel<0, false, false, 3><<<gproj, blk, SMEM3>>>(x1, wq, Q,  N_TOT, D_DIM, D_DIM, nullptr);
    gemm_kernel<0, false, false, 3><<<gproj, blk, SMEM3>>>(x2, wk, Kp, N_TOT, D_DIM, D_DIM, nullptr);
    gemm_kernel<0, false, false, 3><<<gproj, blk, SMEM3>>>(x1, wv, V,  N_TOT, D_DIM, D_DIM, nullptr);
    // 2. logits S = leaky(Q @ K^T)  (3xTF32: logit ABSOLUTE error is sensitive)
    gemm_kernel<1, true, false, 3><<<glog, blk, SMEM3>>>(Q, Kp, S, N_TOT, N_TOT, D_DIM, nullptr);
    // 3. per-row softmax stats
    rowstats_kernel<<<N_TOT, 256>>>(S, roff);
    // 4. out = softmax(S) @ V   (exp fused into staging; 2xTF32: P exact-split, V~tf32)
    gemm_kernel<0, false, true, 2><<<gproj, blk, SMEM2>>>(S, V, out, N_TOT, D_DIM, N_TOT, roff);
}

// round 16
// speedup vs baseline: 1.2981x; 1.2981x over previous
#include <cuda_runtime.h>
#include <cuda_bf16.h>
#include <cstdint>

#define N_TOT 8192
#define D_DIM 512

// ---------------- scratch (static device globals: allocation-free) ----------
__device__ __nv_bfloat16 g_Qh[N_TOT * D_DIM];
__device__ __nv_bfloat16 g_Ql[N_TOT * D_DIM];
__device__ __nv_bfloat16 g_Kh[N_TOT * D_DIM];
__device__ __nv_bfloat16 g_Kl[N_TOT * D_DIM];
__device__ float         g_V [N_TOT * D_DIM];
__device__ __nv_bfloat16 g_VTh[D_DIM * N_TOT];   // V^T split hi [512, 8192]
__device__ __nv_bfloat16 g_VTl[D_DIM * N_TOT];   // V^T split lo
__device__ float g_S[67108864];                  // 8192 * 8192
__device__ float g_roff[N_TOT];

// ---------------- helpers ---------------------------------------------------
__device__ __forceinline__ float to_tf32(float x) {
    float r;
    asm("cvt.rna.tf32.f32 %0, %1;" : "=f"(r) : "f"(x));
    return r;
}

__device__ __forceinline__ float fast_exp2(float x) {
    float y;
    asm("ex2.approx.ftz.f32 %0, %1;" : "=f"(y) : "f"(x));
    return y;
}

__device__ __forceinline__ void mma_tf32(float* c, const uint32_t* a, const uint32_t* b) {
    asm volatile(
        "mma.sync.aligned.m16n8k8.row.col.f32.tf32.tf32.f32 "
        "{%0,%1,%2,%3}, {%4,%5,%6,%7}, {%8,%9}, {%0,%1,%2,%3};\n"
        : "+f"(c[0]), "+f"(c[1]), "+f"(c[2]), "+f"(c[3])
        : "r"(a[0]), "r"(a[1]), "r"(a[2]), "r"(a[3]), "r"(b[0]), "r"(b[1]));
}

// bf16 m16n8k16: K=16 per instruction, same reg shape as tf32 m16n8k8
__device__ __forceinline__ void mma_bf16(float* c, const uint32_t* a, const uint32_t* b) {
    asm volatile(
        "mma.sync.aligned.m16n8k16.row.col.f32.bf16.bf16.f32 "
        "{%0,%1,%2,%3}, {%4,%5,%6,%7}, {%8,%9}, {%0,%1,%2,%3};\n"
        : "+f"(c[0]), "+f"(c[1]), "+f"(c[2]), "+f"(c[3])
        : "r"(a[0]), "r"(a[1]), "r"(a[2]), "r"(a[3]), "r"(b[0]), "r"(b[1]));
}

__device__ __forceinline__ void split_bf16(float v, __nv_bfloat16& h, __nv_bfloat16& l) {
    h = __float2bfloat16_rn(v);
    l = __float2bfloat16_rn(v - __bfloat162float(h));
}

// ================= big GEMMs: split-bf16 NT, CTA 128x128x32 =================
// C[M,N] = op(A)[M,K] @ B[N,K]^T; all SMEM tiles K-major bf16.
// 3 MMAs per logical m16n8k16: Al*Bh + Ah*Bl + Ah*Bh (fp32 accum).
// 256 threads, 8 warps (64x32 warp tiles), 2 CTAs/SM.
#define QBM 128
#define QBN 128
#define QBK 32
#define QSTR 40          // bf16 elems per SMEM row (32 + 8 pad) -> 20 words

// ---- QK: A,B pre-split bf16 in GMEM; epilogue leaky -> S fp32 --------------
__global__ void __launch_bounds__(256, 2)
qk_gemm(const __nv_bfloat16* __restrict__ Ah_g, const __nv_bfloat16* __restrict__ Al_g,
        const __nv_bfloat16* __restrict__ Bh_g, const __nv_bfloat16* __restrict__ Bl_g,
        float* __restrict__ S) {
    __shared__ __nv_bfloat16 sAh[QBM * QSTR], sAl[QBM * QSTR];
    __shared__ __nv_bfloat16 sBh[QBN * QSTR], sBl[QBN * QSTR];

    const int tid  = threadIdx.x;
    const int lane = tid & 31;
    const int warp = tid >> 5;
    const int wm   = warp >> 2;
    const int wn   = warp & 3;
    const int tg   = lane >> 2;
    const int tig  = lane & 3;

    const int m0 = blockIdx.y * QBM;
    const int n0 = blockIdx.x * QBN;

    float acc[4][4][4];
#pragma unroll
    for (int a = 0; a < 4; a++)
#pragma unroll
        for (int b = 0; b < 4; b++)
#pragma unroll
            for (int c = 0; c < 4; c++) acc[a][b][c] = 0.f;

    for (int k0 = 0; k0 < D_DIM; k0 += QBK) {
        __syncthreads();
        // stage: 128 rows x 32 bf16 per buffer; uint4 = 8 bf16
#pragma unroll
        for (int i = 0; i < 2; i++) {
            int f = tid + i * 256;
            int r = f >> 2, c8 = (f & 3) * 8;
            size_t ga = (size_t)(m0 + r) * D_DIM + k0 + c8;
            size_t gb = (size_t)(n0 + r) * D_DIM + k0 + c8;
            *(uint4*)(&sAh[r * QSTR + c8]) = *(const uint4*)(Ah_g + ga);
            *(uint4*)(&sAl[r * QSTR + c8]) = *(const uint4*)(Al_g + ga);
            *(uint4*)(&sBh[r * QSTR + c8]) = *(const uint4*)(Bh_g + gb);
            *(uint4*)(&sBl[r * QSTR + c8]) = *(const uint4*)(Bl_g + gb);
        }
        __syncthreads();

        const uint32_t* Ah32 = (const uint32_t*)sAh;
        const uint32_t* Al32 = (const uint32_t*)sAl;
        const uint32_t* Bh32 = (const uint32_t*)sBh;
        const uint32_t* Bl32 = (const uint32_t*)sBl;

#pragma unroll
        for (int kk = 0; kk < 2; kk++) {
            const int kw = kk * 8;   // word offset of this K=16 slab
            uint32_t bh[4][2], bl[4][2];
#pragma unroll
            for (int nt = 0; nt < 4; nt++) {
                int idx = (wn * 32 + nt * 8 + tg) * 20 + kw + tig;
                bh[nt][0] = Bh32[idx];     bh[nt][1] = Bh32[idx + 4];
                bl[nt][0] = Bl32[idx];     bl[nt][1] = Bl32[idx + 4];
            }
#pragma unroll
            for (int mt = 0; mt < 4; mt++) {
                int idx = (wm * 64 + mt * 16 + tg) * 20 + kw + tig;
                uint32_t ah[4], al[4];
                ah[0] = Ah32[idx];        ah[1] = Ah32[idx + 160];
                ah[2] = Ah32[idx + 4];    ah[3] = Ah32[idx + 164];
                al[0] = Al32[idx];        al[1] = Al32[idx + 160];
                al[2] = Al32[idx + 4];    al[3] = Al32[idx + 164];
#pragma unroll
                for (int nt = 0; nt < 4; nt++) {
                    mma_bf16(acc[mt][nt], al, bh[nt]);   // lo*hi
                    mma_bf16(acc[mt][nt], ah, bl[nt]);   // hi*lo
                    mma_bf16(acc[mt][nt], ah, bh[nt]);   // hi*hi
                }
            }
        }
    }

    float* Cblk = S + (size_t)(m0 + wm * 64) * N_TOT + n0 + wn * 32;
#pragma unroll
    for (int mt = 0; mt < 4; mt++) {
#pragma unroll
        for (int nt = 0; nt < 4; nt++) {
            int r = mt * 16 + tg;
            int c = nt * 8 + 2 * tig;
            float v0 = acc[mt][nt][0], v1 = acc[mt][nt][1];
            float v2 = acc[mt][nt][2], v3 = acc[mt][nt][3];
            v0 = v0 > 0.f ? v0 : 0.01f * v0;
            v1 = v1 > 0.f ? v1 : 0.01f * v1;
            v2 = v2 > 0.f ? v2 : 0.01f * v2;
            v3 = v3 > 0.f ? v3 : 0.01f * v3;
            *(float2*)(Cblk + (size_t)r * N_TOT + c)       = make_float2(v0, v1);
            *(float2*)(Cblk + (size_t)(r + 8) * N_TOT + c) = make_float2(v2, v3);
        }
    }
}

// ---- PV: A = softmax(S) built on the fly (fp32->exp->split); B = VT split --
__global__ void __launch_bounds__(256, 2)
pv_gemm(const float* __restrict__ Sp,
        const __nv_bfloat16* __restrict__ Bh_g, const __nv_bfloat16* __restrict__ Bl_g,
        float* __restrict__ C, const float* __restrict__ rowoff) {
    __shared__ __nv_bfloat16 sAh[QBM * QSTR], sAl[QBM * QSTR];
    __shared__ __nv_bfloat16 sBh[QBN * QSTR], sBl[QBN * QSTR];

    const int tid  = threadIdx.x;
    const int lane = tid & 31;
    const int warp = tid >> 5;
    const int wm   = warp >> 2;
    const int wn   = warp & 3;
    const int tg   = lane >> 2;
    const int tig  = lane & 3;

    const int m0 = blockIdx.y * QBM;
    const int n0 = blockIdx.x * QBN;
    const float L2E = 1.44269504088896f;

    float soff[4];
#pragma unroll
    for (int i = 0; i < 4; i++) soff[i] = rowoff[m0 + ((tid + i * 256) >> 3)];

    float acc[4][4][4];
#pragma unroll
    for (int a = 0; a < 4; a++)
#pragma unroll
        for (int b = 0; b < 4; b++)
#pragma unroll
            for (int c = 0; c < 4; c++) acc[a][b][c] = 0.f;

    for (int k0 = 0; k0 < N_TOT; k0 += QBK) {
        __syncthreads();
        // stage A: 128 x 32 fp32 -> exp2 -> split bf16 hi/lo
#pragma unroll
        for (int i = 0; i < 4; i++) {
            int f = tid + i * 256;
            int r = f >> 3, c4 = (f & 7) * 4;
            float4 v = *(const float4*)(Sp + (size_t)(m0 + r) * N_TOT + k0 + c4);
            v.x = fast_exp2(fmaf(v.x, L2E, soff[i]));
            v.y = fast_exp2(fmaf(v.y, L2E, soff[i]));
            v.z = fast_exp2(fmaf(v.z, L2E, soff[i]));
            v.w = fast_exp2(fmaf(v.w, L2E, soff[i]));
            __nv_bfloat16 h0, h1, h2, h3, l0, l1, l2, l3;
            split_bf16(v.x, h0, l0); split_bf16(v.y, h1, l1);
            split_bf16(v.z, h2, l2); split_bf16(v.w, h3, l3);
            __nv_bfloat162 hp0 = {h0, h1}, hp1 = {h2, h3};
            __nv_bfloat162 lp0 = {l0, l1}, lp1 = {l2, l3};
            *(uint2*)(&sAh[r * QSTR + c4]) =
                make_uint2(*(uint32_t*)&hp0, *(uint32_t*)&hp1);
            *(uint2*)(&sAl[r * QSTR + c4]) =
                make_uint2(*(uint32_t*)&lp0, *(uint32_t*)&lp1);
        }
        // stage B: VT rows (n), K-major, pre-split
#pragma unroll
        for (int i = 0; i < 2; i++) {
            int f = tid + i * 256;
            int r = f >> 2, c8 = (f & 3) * 8;
            size_t gb = (size_t)(n0 + r) * N_TOT + k0 + c8;
            *(uint4*)(&sBh[r * QSTR + c8]) = *(const uint4*)(Bh_g + gb);
            *(uint4*)(&sBl[r * QSTR + c8]) = *(const uint4*)(Bl_g + gb);
        }
        __syncthreads();

        const uint32_t* Ah32 = (const uint32_t*)sAh;
        const uint32_t* Al32 = (const uint32_t*)sAl;
        const uint32_t* Bh32 = (const uint32_t*)sBh;
        const uint32_t* Bl32 = (const uint32_t*)sBl;

#pragma unroll
        for (int kk = 0; kk < 2; kk++) {
            const int kw = kk * 8;
            uint32_t bh[4][2], bl[4][2];
#pragma unroll
            for (int nt = 0; nt < 4; nt++) {
                int idx = (wn * 32 + nt * 8 + tg) * 20 + kw + tig;
                bh[nt][0] = Bh32[idx];     bh[nt][1] = Bh32[idx + 4];
                bl[nt][0] = Bl32[idx];     bl[nt][1] = Bl32[idx + 4];
            }
#pragma unroll
            for (int mt = 0; mt < 4; mt++) {
                int idx = (wm * 64 + mt * 16 + tg) * 20 + kw + tig;
                uint32_t ah[4], al[4];
                ah[0] = Ah32[idx];        ah[1] = Ah32[idx + 160];
                ah[2] = Ah32[idx + 4];    ah[3] = Ah32[idx + 164];
                al[0] = Al32[idx];        al[1] = Al32[idx + 160];
                al[2] = Al32[idx + 4];    al[3] = Al32[idx + 164];
#pragma unroll
                for (int nt = 0; nt < 4; nt++) {
                    mma_bf16(acc[mt][nt], al, bh[nt]);
                    mma_bf16(acc[mt][nt], ah, bl[nt]);
                    mma_bf16(acc[mt][nt], ah, bh[nt]);
                }
            }
        }
    }

    float* Cblk = C + (size_t)(m0 + wm * 64) * D_DIM + n0 + wn * 32;
#pragma unroll
    for (int mt = 0; mt < 4; mt++) {
#pragma unroll
        for (int nt = 0; nt < 4; nt++) {
            int r = mt * 16 + tg;
            int c = nt * 8 + 2 * tig;
            *(float2*)(Cblk + (size_t)r * D_DIM + c) =
                make_float2(acc[mt][nt][0], acc[mt][nt][1]);
            *(float2*)(Cblk + (size_t)(r + 8) * D_DIM + c) =
                make_float2(acc[mt][nt][2], acc[mt][nt][3]);
        }
    }
}

// ============== projections: 3xTF32 NN (R12 config), split/fp32 out =========
#define BM 128
#define BN 128
#define BK 32
#define AS_STRIDE 36
#define BS_STRIDE_NN 136
#define TILE_F 4608

template <bool SPLIT>
__global__ void __launch_bounds__(256, 2)
proj_gemm(const float* __restrict__ A, const float* __restrict__ B,
          float* __restrict__ C, __nv_bfloat16* __restrict__ Ch,
          __nv_bfloat16* __restrict__ Cl, int M, int N, int K) {
    extern __shared__ float smem[];
    float* As_h = smem;
    float* As_l = smem + TILE_F;
    float* Bs_h = smem + 2 * TILE_F;
    float* Bs_l = smem + 3 * TILE_F;

    const int tid  = threadIdx.x;
    const int lane = tid & 31;
    const int warp = tid >> 5;
    const int wm   = warp >> 2;
    const int wn   = warp & 3;
    const int tg   = lane >> 2;
    const int tig  = lane & 3;

    const int m0 = blockIdx.y * BM;
    const int n0 = blockIdx.x * BN;

    const float* Ablk = A + (size_t)m0 * K;
    const float* Bblk = B + n0;

    float acc[4][4][4];
#pragma unroll
    for (int a = 0; a < 4; a++)
#pragma unroll
        for (int b = 0; b < 4; b++)
#pragma unroll
            for (int c = 0; c < 4; c++) acc[a][b][c] = 0.f;

    for (int k0 = 0; k0 < K; k0 += BK) {
        __syncthreads();
#pragma unroll
        for (int i = 0; i < 4; i++) {
            int f = tid + i * 256;
            int r = f >> 3, c4 = f & 7;
            float4 v = *(const float4*)(Ablk + (size_t)r * K + k0 + c4 * 4);
            float4 h, l;
            h.x = to_tf32(v.x); l.x = to_tf32(v.x - h.x);
            h.y = to_tf32(v.y); l.y = to_tf32(v.y - h.y);
            h.z = to_tf32(v.z); l.z = to_tf32(v.z - h.z);
            h.w = to_tf32(v.w); l.w = to_tf32(v.w - h.w);
            *(float4*)(&As_h[r * AS_STRIDE + c4 * 4]) = h;
            *(float4*)(&As_l[r * AS_STRIDE + c4 * 4]) = l;
        }
#pragma unroll
        for (int i = 0; i < 4; i++) {
            int f = tid + i * 256;
            int r = f >> 5, c4 = f & 31;
            float4 v = *(const float4*)(Bblk + (size_t)(k0 + r) * N + c4 * 4);
            float4 h, l;
            h.x = to_tf32(v.x); l.x = to_tf32(v.x - h.x);
            h.y = to_tf32(v.y); l.y = to_tf32(v.y - h.y);
            h.z = to_tf32(v.z); l.z = to_tf32(v.z - h.z);
            h.w = to_tf32(v.w); l.w = to_tf32(v.w - h.w);
            *(float4*)(&Bs_h[r * BS_STRIDE_NN + c4 * 4]) = h;
            *(float4*)(&Bs_l[r * BS_STRIDE_NN + c4 * 4]) = l;
        }
        __syncthreads();

#pragma unroll
        for (int kk = 0; kk < 4; kk++) {
            const int k8 = kk * 8;
            uint32_t bh[4][2], bl[4][2];
#pragma unroll
            for (int nt = 0; nt < 4; nt++) {
                int col = wn * 32 + nt * 8 + tg;
                int off0 = (k8 + tig)     * BS_STRIDE_NN + col;
                int off1 = (k8 + 4 + tig) * BS_STRIDE_NN + col;
                bh[nt][0] = __float_as_uint(Bs_h[off0]);
                bh[nt][1] = __float_as_uint(Bs_h[off1]);
                bl[nt][0] = __float_as_uint(Bs_l[off0]);
                bl[nt][1] = __float_as_uint(Bs_l[off1]);
            }
#pragma unroll
            for (int mt = 0; mt < 4; mt++) {
                int off = (wm * 64 + mt * 16 + tg) * AS_STRIDE + k8 + tig;
                uint32_t ah[4], al[4];
                ah[0] = __float_as_uint(As_h[off]);
                ah[1] = __float_as_uint(As_h[off + 8 * AS_STRIDE]);
                ah[2] = __float_as_uint(As_h[off + 4]);
                ah[3] = __float_as_uint(As_h[off + 8 * AS_STRIDE + 4]);
                al[0] = __float_as_uint(As_l[off]);
                al[1] = __float_as_uint(As_l[off + 8 * AS_STRIDE]);
                al[2] = __float_as_uint(As_l[off + 4]);
                al[3] = __float_as_uint(As_l[off + 8 * AS_STRIDE + 4]);
#pragma unroll
                for (int nt = 0; nt < 4; nt++) {
                    mma_tf32(acc[mt][nt], al, bh[nt]);
                    mma_tf32(acc[mt][nt], ah, bl[nt]);
                    mma_tf32(acc[mt][nt], ah, bh[nt]);
                }
            }
        }
    }

#pragma unroll
    for (int mt = 0; mt < 4; mt++) {
#pragma unroll
        for (int nt = 0; nt < 4; nt++) {
            int r = mt * 16 + tg;
            int c = nt * 8 + 2 * tig;
            size_t o0 = (size_t)(m0 + wm * 64 + r) * N + n0 + wn * 32 + c;
            size_t o1 = (size_t)(m0 + wm * 64 + r + 8) * N + n0 + wn * 32 + c;
            if (SPLIT) {
                __nv_bfloat16 h0, h1, h2, h3, l0, l1, l2, l3;
                split_bf16(acc[mt][nt][0], h0, l0);
                split_bf16(acc[mt][nt][1], h1, l1);
                split_bf16(acc[mt][nt][2], h2, l2);
                split_bf16(acc[mt][nt][3], h3, l3);
                *(__nv_bfloat162*)(Ch + o0) = {h0, h1};
                *(__nv_bfloat162*)(Cl + o0) = {l0, l1};
                *(__nv_bfloat162*)(Ch + o1) = {h2, h3};
                *(__nv_bfloat162*)(Cl + o1) = {l2, l3};
            } else {
                *(float2*)(C + o0) = make_float2(acc[mt][nt][0], acc[mt][nt][1]);
                *(float2*)(C + o1) = make_float2(acc[mt][nt][2], acc[mt][nt][3]);
            }
        }
    }
}

// ---------------- V transpose + split: VT[n][k] = split(V[k][n]) ------------
__global__ void transpose_split(const float* __restrict__ in,
                                __nv_bfloat16* __restrict__ outh,
                                __nv_bfloat16* __restrict__ outl) {
    __shared__ float t[32][33];
    const int bx = blockIdx.x * 32;   // n (512)
    const int by = blockIdx.y * 32;   // k (8192)
    const int x = threadIdx.x, y = threadIdx.y;
#pragma unroll
    for (int j = 0; j < 4; j++)
        t[y + j * 8][x] = in[(size_t)(by + y + j * 8) * D_DIM + bx + x];
    __syncthreads();
#pragma unroll
    for (int j = 0; j < 4; j++) {
        float v = t[x][y + j * 8];
        __nv_bfloat16 h, l;
        split_bf16(v, h, l);
        size_t o = (size_t)(bx + y + j * 8) * N_TOT + by + x;
        outh[o] = h;
        outl[o] = l;
    }
}

// ---------------- row stats: rowoff = -(max*log2e + log2(sum exp)) ----------
__global__ void rowstats_kernel(const float* __restrict__ S, float* __restrict__ roff) {
    __shared__ float red[8];
    const int row = blockIdx.x;
    const int tid = threadIdx.x;
    const float* p = S + (size_t)row * N_TOT;
    const float L2E = 1.44269504088896f;

    float v[32];
    float m = -3.402823e38f;
#pragma unroll
    for (int i = 0; i < 32; i++) {
        v[i] = p[tid + (i << 8)];
        m = fmaxf(m, v[i]);
    }
#pragma unroll
    for (int o = 16; o; o >>= 1) m = fmaxf(m, __shfl_xor_sync(0xffffffffu, m, o));
    if ((tid & 31) == 0) red[tid >> 5] = m;
    __syncthreads();
    m = red[0];
#pragma unroll
    for (int w = 1; w < 8; w++) m = fmaxf(m, red[w]);
    __syncthreads();

    float s = 0.f;
#pragma unroll
    for (int i = 0; i < 32; i++) s += fast_exp2((v[i] - m) * L2E);
#pragma unroll
    for (int o = 16; o; o >>= 1) s += __shfl_xor_sync(0xffffffffu, s, o);
    if ((tid & 31) == 0) red[tid >> 5] = s;
    __syncthreads();
    if (tid == 0) {
        float tot = 0.f;
#pragma unroll
        for (int w = 0; w < 8; w++) tot += red[w];
        roff[row] = -(m * L2E + __log2f(tot));
    }
}

// ---------------- launch -----------------------------------------------------
extern "C" void kernel_launch(void* const* d_in, const int* in_sizes, int n_in,
                              void* d_out, int out_size) {
    const float* x1 = (const float*)d_in[0];
    const float* x2 = (const float*)d_in[1];
    const float* wq = (const float*)d_in[2];
    const float* wk = (const float*)d_in[3];
    const float* wv = (const float*)d_in[4];
    float* out = (float*)d_out;

    __nv_bfloat16 *Qh, *Ql, *Kh, *Kl, *VTh, *VTl;
    float *V, *S, *roff;
    cudaGetSymbolAddress((void**)&Qh,  g_Qh);
    cudaGetSymbolAddress((void**)&Ql,  g_Ql);
    cudaGetSymbolAddress((void**)&Kh,  g_Kh);
    cudaGetSymbolAddress((void**)&Kl,  g_Kl);
    cudaGetSymbolAddress((void**)&V,   g_V);
    cudaGetSymbolAddress((void**)&VTh, g_VTh);
    cudaGetSymbolAddress((void**)&VTl, g_VTl);
    cudaGetSymbolAddress((void**)&S,   g_S);
    cudaGetSymbolAddress((void**)&roff, g_roff);

    constexpr int PROJ_SMEM = 4 * TILE_F * 4;   // 73728 B
    cudaFuncSetAttribute(proj_gemm<true>,
                         cudaFuncAttributeMaxDynamicSharedMemorySize, PROJ_SMEM);
    cudaFuncSetAttribute(proj_gemm<false>,
                         cudaFuncAttributeMaxDynamicSharedMemorySize, PROJ_SMEM);

    dim3 blk(256);
    dim3 gproj(D_DIM / BN, N_TOT / BM);     // (4, 64)
    dim3 gqk(N_TOT / QBN, N_TOT / QBM);     // (64, 64)
    dim3 gpv(D_DIM / QBN, N_TOT / QBM);     // (4, 64)

    // 1. projections (3xTF32, fp32-accurate); Q,K emitted pre-split bf16
    proj_gemm<true ><<<gproj, blk, PROJ_SMEM>>>(x1, wq, nullptr, Qh, Ql, N_TOT, D_DIM, D_DIM);
    proj_gemm<true ><<<gproj, blk, PROJ_SMEM>>>(x2, wk, nullptr, Kh, Kl, N_TOT, D_DIM, D_DIM);
    proj_gemm<false><<<gproj, blk, PROJ_SMEM>>>(x1, wv, V, nullptr, nullptr, N_TOT, D_DIM, D_DIM);
    // 2. transpose + split V -> VTh/VTl
    transpose_split<<<dim3(D_DIM / 32, N_TOT / 32), dim3(32, 8)>>>(V, VTh, VTl);
    // 3. logits S = leaky(Q @ K^T)  — split-bf16 m16n8k16, 3 terms
    qk_gemm<<<gqk, blk>>>(Qh, Ql, Kh, Kl, S);
    // 4. per-row softmax stats
    rowstats_kernel<<<N_TOT, 256>>>(S, roff);
    // 5. out = softmax(S) @ V — P built on the fly, split-bf16, 3 terms
    pv_gemm<<<gpv, blk>>>(S, VTh, VTl, out, roff);
}

// round 17
// speedup vs baseline: 1.6310x; 1.2564x over previous
#include <cuda_runtime.h>
#include <cuda_bf16.h>
#include <cuda_fp16.h>
#include <cstdint>

#define N_TOT 8192
#define D_DIM 512

// ---------------- scratch (static device globals: allocation-free) ----------
__device__ __nv_bfloat16 g_Qh[N_TOT * D_DIM];
__device__ __nv_bfloat16 g_Ql[N_TOT * D_DIM];
__device__ __nv_bfloat16 g_Kh[N_TOT * D_DIM];
__device__ __nv_bfloat16 g_Kl[N_TOT * D_DIM];
__device__ float         g_V [N_TOT * D_DIM];
__device__ __half        g_VT[D_DIM * N_TOT];    // V^T fp16 [512, 8192]
__device__ float g_S[67108864];                  // 8192 * 8192
__device__ float g_roff[N_TOT];

// ---------------- helpers ---------------------------------------------------
__device__ __forceinline__ uint32_t smem_u32(const void* p) {
    uint32_t a;
    asm("{ .reg .u64 t; cvta.to.shared.u64 t, %1; cvt.u32.u64 %0, t; }"
        : "=r"(a) : "l"(p));
    return a;
}

__device__ __forceinline__ float to_tf32(float x) {
    float r;
    asm("cvt.rna.tf32.f32 %0, %1;" : "=f"(r) : "f"(x));
    return r;
}

__device__ __forceinline__ float fast_exp2(float x) {
    float y;
    asm("ex2.approx.ftz.f32 %0, %1;" : "=f"(y) : "f"(x));
    return y;
}

__device__ __forceinline__ void mma_tf32(float* c, const uint32_t* a, const uint32_t* b) {
    asm volatile(
        "mma.sync.aligned.m16n8k8.row.col.f32.tf32.tf32.f32 "
        "{%0,%1,%2,%3}, {%4,%5,%6,%7}, {%8,%9}, {%0,%1,%2,%3};\n"
        : "+f"(c[0]), "+f"(c[1]), "+f"(c[2]), "+f"(c[3])
        : "r"(a[0]), "r"(a[1]), "r"(a[2]), "r"(a[3]), "r"(b[0]), "r"(b[1]));
}

__device__ __forceinline__ void mma_bf16(float* c, const uint32_t* a, const uint32_t* b) {
    asm volatile(
        "mma.sync.aligned.m16n8k16.row.col.f32.bf16.bf16.f32 "
        "{%0,%1,%2,%3}, {%4,%5,%6,%7}, {%8,%9}, {%0,%1,%2,%3};\n"
        : "+f"(c[0]), "+f"(c[1]), "+f"(c[2]), "+f"(c[3])
        : "r"(a[0]), "r"(a[1]), "r"(a[2]), "r"(a[3]), "r"(b[0]), "r"(b[1]));
}

__device__ __forceinline__ void mma_f16(float* c, const uint32_t* a, const uint32_t* b) {
    asm volatile(
        "mma.sync.aligned.m16n8k16.row.col.f32.f16.f16.f32 "
        "{%0,%1,%2,%3}, {%4,%5,%6,%7}, {%8,%9}, {%0,%1,%2,%3};\n"
        : "+f"(c[0]), "+f"(c[1]), "+f"(c[2]), "+f"(c[3])
        : "r"(a[0]), "r"(a[1]), "r"(a[2]), "r"(a[3]), "r"(b[0]), "r"(b[1]));
}

__device__ __forceinline__ void ldmx4(uint32_t& r0, uint32_t& r1, uint32_t& r2,
                                      uint32_t& r3, uint32_t addr) {
    asm volatile("ldmatrix.sync.aligned.m8n8.x4.shared.b16 {%0,%1,%2,%3}, [%4];"
                 : "=r"(r0), "=r"(r1), "=r"(r2), "=r"(r3) : "r"(addr));
}

__device__ __forceinline__ void split_bf16(float v, __nv_bfloat16& h, __nv_bfloat16& l) {
    h = __float2bfloat16_rn(v);
    l = __float2bfloat16_rn(v - __bfloat162float(h));
}

// ================= big GEMMs: NT, CTA 128x128x32, ldmatrix fragments ========
#define QBM 128
#define QBN 128
#define QBK 32
#define QSTR 40   // b16 elems per SMEM row (32 + 8 pad): 80B rows, ldmatrix conflict-free

// ---- QK: 3-term split-bf16; A,B pre-split in GMEM; leaky epilogue ----------
__global__ void __launch_bounds__(256, 2)
qk_gemm(const __nv_bfloat16* __restrict__ Ah_g, const __nv_bfloat16* __restrict__ Al_g,
        const __nv_bfloat16* __restrict__ Bh_g, const __nv_bfloat16* __restrict__ Bl_g,
        float* __restrict__ S) {
    __shared__ __nv_bfloat16 sAh[QBM * QSTR], sAl[QBM * QSTR];
    __shared__ __nv_bfloat16 sBh[QBN * QSTR], sBl[QBN * QSTR];

    const int tid  = threadIdx.x;
    const int lane = tid & 31;
    const int warp = tid >> 5;
    const int wm   = warp >> 2;
    const int wn   = warp & 3;
    const int tg   = lane >> 2;
    const int tig  = lane & 3;

    const int m0 = blockIdx.y * QBM;
    const int n0 = blockIdx.x * QBN;

    // ldmatrix per-lane element offsets
    const int aOff = (wm * 64 + (lane & 15)) * QSTR + ((lane >> 4) << 3);
    const int bOff = (wn * 32 + ((lane >> 4) << 3) + (lane & 7)) * QSTR
                   + (((lane >> 3) & 1) << 3);
    const uint32_t sAh_b = smem_u32(sAh), sAl_b = smem_u32(sAl);
    const uint32_t sBh_b = smem_u32(sBh), sBl_b = smem_u32(sBl);

    float acc[4][4][4];
#pragma unroll
    for (int a = 0; a < 4; a++)
#pragma unroll
        for (int b = 0; b < 4; b++)
#pragma unroll
            for (int c = 0; c < 4; c++) acc[a][b][c] = 0.f;

    for (int k0 = 0; k0 < D_DIM; k0 += QBK) {
        __syncthreads();
#pragma unroll
        for (int i = 0; i < 2; i++) {
            int f = tid + i * 256;
            int r = f >> 2, c8 = (f & 3) * 8;
            size_t ga = (size_t)(m0 + r) * D_DIM + k0 + c8;
            size_t gb = (size_t)(n0 + r) * D_DIM + k0 + c8;
            *(uint4*)(&sAh[r * QSTR + c8]) = *(const uint4*)(Ah_g + ga);
            *(uint4*)(&sAl[r * QSTR + c8]) = *(const uint4*)(Al_g + ga);
            *(uint4*)(&sBh[r * QSTR + c8]) = *(const uint4*)(Bh_g + gb);
            *(uint4*)(&sBl[r * QSTR + c8]) = *(const uint4*)(Bl_g + gb);
        }
        __syncthreads();

#pragma unroll
        for (int kk = 0; kk < 2; kk++) {
            const int ke = kk * 16;   // element offset of K=16 slab
            uint32_t bh[4][2], bl[4][2];
#pragma unroll
            for (int p = 0; p < 2; p++) {
                uint32_t o = (uint32_t)(bOff + p * 16 * QSTR + ke) * 2;
                ldmx4(bh[2*p][0], bh[2*p][1], bh[2*p+1][0], bh[2*p+1][1], sBh_b + o);
                ldmx4(bl[2*p][0], bl[2*p][1], bl[2*p+1][0], bl[2*p+1][1], sBl_b + o);
            }
#pragma unroll
            for (int mt = 0; mt < 4; mt++) {
                uint32_t o = (uint32_t)(aOff + mt * 16 * QSTR + ke) * 2;
                uint32_t ah[4], al[4];
                ldmx4(ah[0], ah[1], ah[2], ah[3], sAh_b + o);
                ldmx4(al[0], al[1], al[2], al[3], sAl_b + o);
#pragma unroll
                for (int nt = 0; nt < 4; nt++) {
                    mma_bf16(acc[mt][nt], al, bh[nt]);   // lo*hi
                    mma_bf16(acc[mt][nt], ah, bl[nt]);   // hi*lo
                    mma_bf16(acc[mt][nt], ah, bh[nt]);   // hi*hi
                }
            }
        }
    }

    float* Cblk = S + (size_t)(m0 + wm * 64) * N_TOT + n0 + wn * 32;
#pragma unroll
    for (int mt = 0; mt < 4; mt++) {
#pragma unroll
        for (int nt = 0; nt < 4; nt++) {
            int r = mt * 16 + tg;
            int c = nt * 8 + 2 * tig;
            float v0 = acc[mt][nt][0], v1 = acc[mt][nt][1];
            float v2 = acc[mt][nt][2], v3 = acc[mt][nt][3];
            v0 = v0 > 0.f ? v0 : 0.01f * v0;
            v1 = v1 > 0.f ? v1 : 0.01f * v1;
            v2 = v2 > 0.f ? v2 : 0.01f * v2;
            v3 = v3 > 0.f ? v3 : 0.01f * v3;
            *(float2*)(Cblk + (size_t)r * N_TOT + c)       = make_float2(v0, v1);
            *(float2*)(Cblk + (size_t)(r + 8) * N_TOT + c) = make_float2(v2, v3);
        }
    }
}

// ---- PV: 2-term fp16 (P exact-split on the fly; V single fp16) -------------
__global__ void __launch_bounds__(256, 2)
pv_gemm(const float* __restrict__ Sp, const __half* __restrict__ Bh_g,
        float* __restrict__ C, const float* __restrict__ rowoff) {
    __shared__ __half sAh[QBM * QSTR], sAl[QBM * QSTR];
    __shared__ __half sBh[QBN * QSTR];

    const int tid  = threadIdx.x;
    const int lane = tid & 31;
    const int warp = tid >> 5;
    const int wm   = warp >> 2;
    const int wn   = warp & 3;
    const int tg   = lane >> 2;
    const int tig  = lane & 3;

    const int m0 = blockIdx.y * QBM;
    const int n0 = blockIdx.x * QBN;
    const float L2E = 1.44269504088896f;

    const int aOff = (wm * 64 + (lane & 15)) * QSTR + ((lane >> 4) << 3);
    const int bOff = (wn * 32 + ((lane >> 4) << 3) + (lane & 7)) * QSTR
                   + (((lane >> 3) & 1) << 3);
    const uint32_t sAh_b = smem_u32(sAh), sAl_b = smem_u32(sAl);
    const uint32_t sBh_b = smem_u32(sBh);

    float soff[4];
#pragma unroll
    for (int i = 0; i < 4; i++) soff[i] = rowoff[m0 + ((tid + i * 256) >> 3)];

    float acc[4][4][4];
#pragma unroll
    for (int a = 0; a < 4; a++)
#pragma unroll
        for (int b = 0; b < 4; b++)
#pragma unroll
            for (int c = 0; c < 4; c++) acc[a][b][c] = 0.f;

    for (int k0 = 0; k0 < N_TOT; k0 += QBK) {
        __syncthreads();
        // stage A: 128 x 32 fp32 -> exp2 -> fp16 hi/lo
#pragma unroll
        for (int i = 0; i < 4; i++) {
            int f = tid + i * 256;
            int r = f >> 3, c4 = (f & 7) * 4;
            float4 v = *(const float4*)(Sp + (size_t)(m0 + r) * N_TOT + k0 + c4);
            v.x = fast_exp2(fmaf(v.x, L2E, soff[i]));
            v.y = fast_exp2(fmaf(v.y, L2E, soff[i]));
            v.z = fast_exp2(fmaf(v.z, L2E, soff[i]));
            v.w = fast_exp2(fmaf(v.w, L2E, soff[i]));
            __half2 h0 = __float22half2_rn(make_float2(v.x, v.y));
            __half2 h1 = __float22half2_rn(make_float2(v.z, v.w));
            __half2 l0 = __float22half2_rn(make_float2(
                v.x - __half2float(h0.x), v.y - __half2float(h0.y)));
            __half2 l1 = __float22half2_rn(make_float2(
                v.z - __half2float(h1.x), v.w - __half2float(h1.y)));
            *(uint2*)(&sAh[r * QSTR + c4]) =
                make_uint2(*(uint32_t*)&h0, *(uint32_t*)&h1);
            *(uint2*)(&sAl[r * QSTR + c4]) =
                make_uint2(*(uint32_t*)&l0, *(uint32_t*)&l1);
        }
        // stage B: VT rows (n), K-major fp16
#pragma unroll
        for (int i = 0; i < 2; i++) {
            int f = tid + i * 256;
            int r = f >> 2, c8 = (f & 3) * 8;
            *(uint4*)(&sBh[r * QSTR + c8]) =
                *(const uint4*)(Bh_g + (size_t)(n0 + r) * N_TOT + k0 + c8);
        }
        __syncthreads();

#pragma unroll
        for (int kk = 0; kk < 2; kk++) {
            const int ke = kk * 16;
            uint32_t bh[4][2];
#pragma unroll
            for (int p = 0; p < 2; p++) {
                uint32_t o = (uint32_t)(bOff + p * 16 * QSTR + ke) * 2;
                ldmx4(bh[2*p][0], bh[2*p][1], bh[2*p+1][0], bh[2*p+1][1], sBh_b + o);
            }
#pragma unroll
            for (int mt = 0; mt < 4; mt++) {
                uint32_t o = (uint32_t)(aOff + mt * 16 * QSTR + ke) * 2;
                uint32_t ah[4], al[4];
                ldmx4(ah[0], ah[1], ah[2], ah[3], sAh_b + o);
                ldmx4(al[0], al[1], al[2], al[3], sAl_b + o);
#pragma unroll
                for (int nt = 0; nt < 4; nt++) {
                    mma_f16(acc[mt][nt], al, bh[nt]);   // lo*V
                    mma_f16(acc[mt][nt], ah, bh[nt]);   // hi*V
                }
            }
        }
    }

    float* Cblk = C + (size_t)(m0 + wm * 64) * D_DIM + n0 + wn * 32;
#pragma unroll
    for (int mt = 0; mt < 4; mt++) {
#pragma unroll
        for (int nt = 0; nt < 4; nt++) {
            int r = mt * 16 + tg;
            int c = nt * 8 + 2 * tig;
            *(float2*)(Cblk + (size_t)r * D_DIM + c) =
                make_float2(acc[mt][nt][0], acc[mt][nt][1]);
            *(float2*)(Cblk + (size_t)(r + 8) * D_DIM + c) =
                make_float2(acc[mt][nt][2], acc[mt][nt][3]);
        }
    }
}

// ============== projections: 3xTF32 NN (R12 config), split/fp32 out =========
#define BM 128
#define BN 128
#define BK 32
#define AS_STRIDE 36
#define BS_STRIDE_NN 136
#define TILE_F 4608

template <bool SPLIT>
__global__ void __launch_bounds__(256, 2)
proj_gemm(const float* __restrict__ A, const float* __restrict__ B,
          float* __restrict__ C, __nv_bfloat16* __restrict__ Ch,
          __nv_bfloat16* __restrict__ Cl, int M, int N, int K) {
    extern __shared__ float smem[];
    float* As_h = smem;
    float* As_l = smem + TILE_F;
    float* Bs_h = smem + 2 * TILE_F;
    float* Bs_l = smem + 3 * TILE_F;

    const int tid  = threadIdx.x;
    const int lane = tid & 31;
    const int warp = tid >> 5;
    const int wm   = warp >> 2;
    const int wn   = warp & 3;
    const int tg   = lane >> 2;
    const int tig  = lane & 3;

    const int m0 = blockIdx.y * BM;
    const int n0 = blockIdx.x * BN;

    const float* Ablk = A + (size_t)m0 * K;
    const float* Bblk = B + n0;

    float acc[4][4][4];
#pragma unroll
    for (int a = 0; a < 4; a++)
#pragma unroll
        for (int b = 0; b < 4; b++)
#pragma unroll
            for (int c = 0; c < 4; c++) acc[a][b][c] = 0.f;

    for (int k0 = 0; k0 < K; k0 += BK) {
        __syncthreads();
#pragma unroll
        for (int i = 0; i < 4; i++) {
            int f = tid + i * 256;
            int r = f >> 3, c4 = f & 7;
            float4 v = *(const float4*)(Ablk + (size_t)r * K + k0 + c4 * 4);
            float4 h, l;
            h.x = to_tf32(v.x); l.x = to_tf32(v.x - h.x);
            h.y = to_tf32(v.y); l.y = to_tf32(v.y - h.y);
            h.z = to_tf32(v.z); l.z = to_tf32(v.z - h.z);
            h.w = to_tf32(v.w); l.w = to_tf32(v.w - h.w);
            *(float4*)(&As_h[r * AS_STRIDE + c4 * 4]) = h;
            *(float4*)(&As_l[r * AS_STRIDE + c4 * 4]) = l;
        }
#pragma unroll
        for (int i = 0; i < 4; i++) {
            int f = tid + i * 256;
            int r = f >> 5, c4 = f & 31;
            float4 v = *(const float4*)(Bblk + (size_t)(k0 + r) * N + c4 * 4);
            float4 h, l;
            h.x = to_tf32(v.x); l.x = to_tf32(v.x - h.x);
            h.y = to_tf32(v.y); l.y = to_tf32(v.y - h.y);
            h.z = to_tf32(v.z); l.z = to_tf32(v.z - h.z);
            h.w = to_tf32(v.w); l.w = to_tf32(v.w - h.w);
            *(float4*)(&Bs_h[r * BS_STRIDE_NN + c4 * 4]) = h;
            *(float4*)(&Bs_l[r * BS_STRIDE_NN + c4 * 4]) = l;
        }
        __syncthreads();

#pragma unroll
        for (int kk = 0; kk < 4; kk++) {
            const int k8 = kk * 8;
            uint32_t bh[4][2], bl[4][2];
#pragma unroll
            for (int nt = 0; nt < 4; nt++) {
                int col = wn * 32 + nt * 8 + tg;
                int off0 = (k8 + tig)     * BS_STRIDE_NN + col;
                int off1 = (k8 + 4 + tig) * BS_STRIDE_NN + col;
                bh[nt][0] = __float_as_uint(Bs_h[off0]);
                bh[nt][1] = __float_as_uint(Bs_h[off1]);
                bl[nt][0] = __float_as_uint(Bs_l[off0]);
                bl[nt][1] = __float_as_uint(Bs_l[off1]);
            }
#pragma unroll
            for (int mt = 0; mt < 4; mt++) {
                int off = (wm * 64 + mt * 16 + tg) * AS_STRIDE + k8 + tig;
                uint32_t ah[4], al[4];
                ah[0] = __float_as_uint(As_h[off]);
                ah[1] = __float_as_uint(As_h[off + 8 * AS_STRIDE]);
                ah[2] = __float_as_uint(As_h[off + 4]);
                ah[3] = __float_as_uint(As_h[off + 8 * AS_STRIDE + 4]);
                al[0] = __float_as_uint(As_l[off]);
                al[1] = __float_as_uint(As_l[off + 8 * AS_STRIDE]);
                al[2] = __float_as_uint(As_l[off + 4]);
                al[3] = __float_as_uint(As_l[off + 8 * AS_STRIDE + 4]);
#pragma unroll
                for (int nt = 0; nt < 4; nt++) {
                    mma_tf32(acc[mt][nt], al, bh[nt]);
                    mma_tf32(acc[mt][nt], ah, bl[nt]);
                    mma_tf32(acc[mt][nt], ah, bh[nt]);
                }
            }
        }
    }

#pragma unroll
    for (int mt = 0; mt < 4; mt++) {
#pragma unroll
        for (int nt = 0; nt < 4; nt++) {
            int r = mt * 16 + tg;
            int c = nt * 8 + 2 * tig;
            size_t o0 = (size_t)(m0 + wm * 64 + r) * N + n0 + wn * 32 + c;
            size_t o1 = (size_t)(m0 + wm * 64 + r + 8) * N + n0 + wn * 32 + c;
            if (SPLIT) {
                __nv_bfloat16 h0, h1, h2, h3, l0, l1, l2, l3;
                split_bf16(acc[mt][nt][0], h0, l0);
                split_bf16(acc[mt][nt][1], h1, l1);
                split_bf16(acc[mt][nt][2], h2, l2);
                split_bf16(acc[mt][nt][3], h3, l3);
                *(__nv_bfloat162*)(Ch + o0) = {h0, h1};
                *(__nv_bfloat162*)(Cl + o0) = {l0, l1};
                *(__nv_bfloat162*)(Ch + o1) = {h2, h3};
                *(__nv_bfloat162*)(Cl + o1) = {l2, l3};
            } else {
                *(float2*)(C + o0) = make_float2(acc[mt][nt][0], acc[mt][nt][1]);
                *(float2*)(C + o1) = make_float2(acc[mt][nt][2], acc[mt][nt][3]);
            }
        }
    }
}

// ---------------- V transpose -> fp16: VT[n][k] = h(V[k][n]) ----------------
__global__ void transpose_h(const float* __restrict__ in, __half* __restrict__ outh) {
    __shared__ float t[32][33];
    const int bx = blockIdx.x * 32;   // n (512)
    const int by = blockIdx.y * 32;   // k (8192)
    const int x = threadIdx.x, y = threadIdx.y;
#pragma unroll
    for (int j = 0; j < 4; j++)
        t[y + j * 8][x] = in[(size_t)(by + y + j * 8) * D_DIM + bx + x];
    __syncthreads();
#pragma unroll
    for (int j = 0; j < 4; j++)
        outh[(size_t)(bx + y + j * 8) * N_TOT + by + x] = __float2half_rn(t[x][y + j * 8]);
}

// ---------------- row stats: rowoff = -(max*log2e + log2(sum exp)) ----------
__global__ void rowstats_kernel(const float* __restrict__ S, float* __restrict__ roff) {
    __shared__ float red[8];
    const int row = blockIdx.x;
    const int tid = threadIdx.x;
    const float* p = S + (size_t)row * N_TOT;
    const float L2E = 1.44269504088896f;

    float v[32];
    float m = -3.402823e38f;
#pragma unroll
    for (int i = 0; i < 32; i++) {
        v[i] = p[tid + (i << 8)];
        m = fmaxf(m, v[i]);
    }
#pragma unroll
    for (int o = 16; o; o >>= 1) m = fmaxf(m, __shfl_xor_sync(0xffffffffu, m, o));
    if ((tid & 31) == 0) red[tid >> 5] = m;
    __syncthreads();
    m = red[0];
#pragma unroll
    for (int w = 1; w < 8; w++) m = fmaxf(m, red[w]);
    __syncthreads();

    float s = 0.f;
#pragma unroll
    for (int i = 0; i < 32; i++) s += fast_exp2((v[i] - m) * L2E);
#pragma unroll
    for (int o = 16; o; o >>= 1) s += __shfl_xor_sync(0xffffffffu, s, o);
    if ((tid & 31) == 0) red[tid >> 5] = s;
    __syncthreads();
    if (tid == 0) {
        float tot = 0.f;
#pragma unroll
        for (int w = 0; w < 8; w++) tot += red[w];
        roff[row] = -(m * L2E + __log2f(tot));
    }
}

// ---------------- launch -----------------------------------------------------
extern "C" void kernel_launch(void* const* d_in, const int* in_sizes, int n_in,
                              void* d_out, int out_size) {
    const float* x1 = (const float*)d_in[0];
    const float* x2 = (const float*)d_in[1];
    const float* wq = (const float*)d_in[2];
    const float* wk = (const float*)d_in[3];
    const float* wv = (const float*)d_in[4];
    float* out = (float*)d_out;

    __nv_bfloat16 *Qh, *Ql, *Kh, *Kl;
    __half *VT;
    float *V, *S, *roff;
    cudaGetSymbolAddress((void**)&Qh,  g_Qh);
    cudaGetSymbolAddress((void**)&Ql,  g_Ql);
    cudaGetSymbolAddress((void**)&Kh,  g_Kh);
    cudaGetSymbolAddress((void**)&Kl,  g_Kl);
    cudaGetSymbolAddress((void**)&V,   g_V);
    cudaGetSymbolAddress((void**)&VT,  g_VT);
    cudaGetSymbolAddress((void**)&S,   g_S);
    cudaGetSymbolAddress((void**)&roff, g_roff);

    constexpr int PROJ_SMEM = 4 * TILE_F * 4;   // 73728 B
    cudaFuncSetAttribute(proj_gemm<true>,
                         cudaFuncAttributeMaxDynamicSharedMemorySize, PROJ_SMEM);
    cudaFuncSetAttribute(proj_gemm<false>,
                         cudaFuncAttributeMaxDynamicSharedMemorySize, PROJ_SMEM);

    dim3 blk(256);
    dim3 gproj(D_DIM / BN, N_TOT / BM);     // (4, 64)
    dim3 gqk(N_TOT / QBN, N_TOT / QBM);     // (64, 64)
    dim3 gpv(D_DIM / QBN, N_TOT / QBM);     // (4, 64)

    // 1. projections (3xTF32, fp32-accurate); Q,K emitted pre-split bf16
    proj_gemm<true ><<<gproj, blk, PROJ_SMEM>>>(x1, wq, nullptr, Qh, Ql, N_TOT, D_DIM, D_DIM);
    proj_gemm<true ><<<gproj, blk, PROJ_SMEM>>>(x2, wk, nullptr, Kh, Kl, N_TOT, D_DIM, D_DIM);
    proj_gemm<false><<<gproj, blk, PROJ_SMEM>>>(x1, wv, V, nullptr, nullptr, N_TOT, D_DIM, D_DIM);
    // 2. transpose V -> fp16 VT
    transpose_h<<<dim3(D_DIM / 32, N_TOT / 32), dim3(32, 8)>>>(V, VT);
    // 3. logits S = leaky(Q @ K^T)  — 3-term split-bf16 + ldmatrix
    qk_gemm<<<gqk, blk>>>(Qh, Ql, Kh, Kl, S);
    // 4. per-row softmax stats
    rowstats_kernel<<<N_TOT, 256>>>(S, roff);
    // 5. out = softmax(S) @ V — 2-term fp16 (P split, V single) + ldmatrix
    pv_gemm<<<gpv, blk>>>(S, VT, out, roff);
}